// round 14
// baseline (speedup 1.0000x reference)
#include <cuda_runtime.h>
#include <cuda_fp16.h>
#include <math.h>
#include <stdint.h>

#define Nn 16384
#define Dd 512
#define Kk 1024
#define NUM_ITERS 10
#define TEMPERATURE 0.1f
#define CONCENTRATION 0.1f
#define EPSf 1e-6f

#define NCHUNK 64
#define CHUNK  256

// ---------------- device scratch ----------------
__device__ float  g_cent[Kk * Dd];
__device__ float  g_csq[Kk];
__device__ __align__(16) __half g_fh[Nn * Dd];   // feats fp16 hi
__device__ __align__(16) __half g_fm[Nn * Dd];   // feats fp16 lo
__device__ __align__(16) __half g_ch[Kk * Dd];   // centroid fp16 hi
__device__ __align__(16) __half g_cm[Kk * Dd];   // centroid fp16 lo
__device__ int    g_asg[Nn];
__device__ float  g_bd8[8][Nn];
__device__ int    g_bi8[8][Nn];
__device__ int    g_counts[Kk];
__device__ int    g_offsets[Kk];
__device__ int    g_hist[NCHUNK * Kk];
__device__ int    g_order[Nn];
__device__ float  g_dists[Kk * Dd];
__device__ double g_part1[256];
__device__ double g_part2a[256];
__device__ double g_part2b[256];
__device__ double g_S;

__global__ void copy_init_kernel(const float* __restrict__ feats) {
    int i = blockIdx.x * blockDim.x + threadIdx.x;
    if (i < Kk * Dd) g_cent[i] = feats[i];
}

__global__ void split_feats_kernel(const float* __restrict__ feats) {
    int i = blockIdx.x * blockDim.x + threadIdx.x;
    if (i >= Nn * Dd) return;
    float x = feats[i];
    __half h = __float2half_rn(x);
    __half m = __float2half_rn(x - __half2float(h));
    g_fh[i] = h;
    g_fm[i] = m;
}

// fused: centroid fp16 split + squared norms (warp per centroid row)
__global__ void split_csq_kernel() {
    int warp = (blockIdx.x * blockDim.x + threadIdx.x) >> 5;
    int lane = threadIdx.x & 31;
    if (warp >= Kk) return;
    const float2* r = (const float2*)(g_cent + (size_t)warp * Dd);
    __half2* ch2 = (__half2*)(g_ch + (size_t)warp * Dd);
    __half2* cm2 = (__half2*)(g_cm + (size_t)warp * Dd);
    float s = 0.f;
#pragma unroll
    for (int i = 0; i < Dd / 64; i++) {
        float2 v = r[lane + i * 32];
        __half hx = __float2half_rn(v.x), hy = __float2half_rn(v.y);
        __half mx = __float2half_rn(v.x - __half2float(hx));
        __half my = __float2half_rn(v.y - __half2float(hy));
        ch2[lane + i * 32] = __halves2half2(hx, hy);
        cm2[lane + i * 32] = __halves2half2(mx, my);
        s += v.x * v.x + v.y * v.y;
    }
#pragma unroll
    for (int o = 16; o; o >>= 1) s += __shfl_xor_sync(0xffffffffu, s, o);
    if (lane == 0) g_csq[warp] = s;
}

// ================= mma.sync (HMMA) assignment, cp.async pipelined =========
// Block: 128 points x 128 clusters; grid (128, 8 N-splits); 256 threads.
// dot = xh*ch + xh*cm + xm*ch in fp32 via m16n8k16 fp16 mma.
// 2-stage cp.async double buffer over 8 d-chunks of 64 halves.
#define TM 128
#define TN 128
#define KC 64                  // halves per d-chunk
#define NCHK2 (Dd / KC)        // 8

#define OFF_AH 0
#define OFF_AM (TM * KC * 2)                   // 16384
#define OFF_BH (2 * TM * KC * 2)               // 32768
#define OFF_BM (2 * TM * KC * 2 + TN * KC * 2) // 49152
#define STAGE_BYTES (2 * TM * KC * 2 + 2 * TN * KC * 2)  // 65536
#define SMEM_BYTES (2 * STAGE_BYTES)                     // 131072

__device__ __forceinline__ uint32_t smem_u32(const void* p) {
    uint32_t a;
    asm("{ .reg .u64 t; cvta.to.shared.u64 t, %1; cvt.u32.u64 %0, t; }" : "=r"(a) : "l"(p));
    return a;
}

__device__ __forceinline__ void cp16(uint32_t saddr, const void* gptr) {
    asm volatile("cp.async.cg.shared.global [%0], [%1], 16;"
                 :: "r"(saddr), "l"(gptr) : "memory");
}

__device__ __forceinline__ void ldsm_x4(uint32_t addr, uint32_t& r0, uint32_t& r1,
                                        uint32_t& r2, uint32_t& r3) {
    asm volatile("ldmatrix.sync.aligned.m8n8.x4.shared.b16 {%0,%1,%2,%3}, [%4];"
                 : "=r"(r0), "=r"(r1), "=r"(r2), "=r"(r3) : "r"(addr));
}

__device__ __forceinline__ void mma16816(float* d, const uint32_t* a, const uint32_t* b) {
    asm volatile(
        "mma.sync.aligned.m16n8k16.row.col.f32.f16.f16.f32 "
        "{%0,%1,%2,%3}, {%4,%5,%6,%7}, {%8,%9}, {%0,%1,%2,%3};"
        : "+f"(d[0]), "+f"(d[1]), "+f"(d[2]), "+f"(d[3])
        : "r"(a[0]), "r"(a[1]), "r"(a[2]), "r"(a[3]), "r"(b[0]), "r"(b[1]));
}

extern __shared__ char dsm[];

__global__ void __launch_bounds__(256, 1) assign_mma_kernel() {
    __shared__ float scsq[TN];
    __shared__ float sdist[TM][4];
    __shared__ int   sidx[TM][4];

    int tid = threadIdx.x;
    int lane = tid & 31;
    int w = tid >> 5;
    int wm = w >> 2, wn = w & 3;           // warp grid 2 x 4
    int row0 = blockIdx.x * TM;
    int nbase = blockIdx.y * TN;

    uint32_t sb = smem_u32(dsm);

    if (tid < TN) scsq[tid] = g_csq[nbase + tid];

    float acc[4][4][4];
#pragma unroll
    for (int mt = 0; mt < 4; mt++)
#pragma unroll
        for (int nt = 0; nt < 4; nt++)
#pragma unroll
            for (int r = 0; r < 4; r++) acc[mt][nt][r] = 0.f;

    // per-thread load coordinates (fixed across chunks/stages)
    int lrow = tid >> 3, lgrp = tid & 7;

#define ISSUE_CHUNK(ch_, stg_)                                                     \
    do {                                                                           \
        int d0_ = (ch_) * KC;                                                      \
        uint32_t sbase_ = sb + (stg_) * STAGE_BYTES;                               \
        _Pragma("unroll")                                                          \
        for (int u_ = 0; u_ < 4; u_++) {                                           \
            int row_ = lrow + u_ * 32;                                             \
            uint32_t so_ = (uint32_t)(((row_ << 3) + (lgrp ^ (row_ & 7))) * 16);   \
            size_t goff_ = (size_t)row_ * Dd + d0_ + lgrp * 8;                     \
            cp16(sbase_ + OFF_AH + so_, g_fh + (size_t)row0 * Dd + goff_);         \
            cp16(sbase_ + OFF_AM + so_, g_fm + (size_t)row0 * Dd + goff_);         \
            cp16(sbase_ + OFF_BH + so_, g_ch + (size_t)nbase * Dd + goff_);        \
            cp16(sbase_ + OFF_BM + so_, g_cm + (size_t)nbase * Dd + goff_);        \
        }                                                                          \
        asm volatile("cp.async.commit_group;" ::: "memory");                       \
    } while (0)

    // ldmatrix address components (16B-granule XOR swizzle within 128B rows)
    int arow_b = wm * 64 + (lane & 7) + ((lane >> 3) & 1) * 8;   // + mt*16
    int agrp_h = (lane >> 4);                                    // + ks*2
    int brow_b = wn * 32 + (lane & 7) + ((lane >> 4) << 3);      // + bt*16
    int bgrp_h = ((lane >> 3) & 1);

    ISSUE_CHUNK(0, 0);

    for (int ch2 = 0; ch2 < NCHK2; ch2++) {
        int stg = ch2 & 1;
        if (ch2 + 1 < NCHK2) {
            ISSUE_CHUNK(ch2 + 1, stg ^ 1);
            asm volatile("cp.async.wait_group 1;" ::: "memory");
        } else {
            asm volatile("cp.async.wait_group 0;" ::: "memory");
        }
        __syncthreads();

        uint32_t sbase = sb + stg * STAGE_BYTES;
#pragma unroll
        for (int ks = 0; ks < KC / 16; ks++) {
            uint32_t ah[4][4], am[4][4], bh[4][2], bm[4][2];
#pragma unroll
            for (int mt = 0; mt < 4; mt++) {
                int row = arow_b + mt * 16;
                int grp = ks * 2 + agrp_h;
                uint32_t so = (uint32_t)(((row << 3) + (grp ^ (row & 7))) * 16);
                ldsm_x4(sbase + OFF_AH + so, ah[mt][0], ah[mt][1], ah[mt][2], ah[mt][3]);
                ldsm_x4(sbase + OFF_AM + so, am[mt][0], am[mt][1], am[mt][2], am[mt][3]);
            }
#pragma unroll
            for (int bt = 0; bt < 2; bt++) {
                int row = brow_b + bt * 16;
                int grp = ks * 2 + bgrp_h;
                uint32_t so = (uint32_t)(((row << 3) + (grp ^ (row & 7))) * 16);
                ldsm_x4(sbase + OFF_BH + so, bh[2 * bt][0], bh[2 * bt][1],
                        bh[2 * bt + 1][0], bh[2 * bt + 1][1]);
                ldsm_x4(sbase + OFF_BM + so, bm[2 * bt][0], bm[2 * bt][1],
                        bm[2 * bt + 1][0], bm[2 * bt + 1][1]);
            }
#pragma unroll
            for (int mt = 0; mt < 4; mt++)
#pragma unroll
                for (int nt = 0; nt < 4; nt++) {
                    mma16816(acc[mt][nt], ah[mt], bh[nt]);   // hh
                    mma16816(acc[mt][nt], ah[mt], bm[nt]);   // hm
                    mma16816(acc[mt][nt], am[mt], bh[nt]);   // mh
                }
        }
        __syncthreads();
    }

    // ---------------- epilogue: distances + argmin ----------------
    int q = lane & 3, hr = lane >> 2;
#pragma unroll
    for (int mt = 0; mt < 4; mt++)
#pragma unroll
        for (int half = 0; half < 2; half++) {
            float bd = 3.4e38f;
            int bi = 0;
#pragma unroll
            for (int nt = 0; nt < 4; nt++)
#pragma unroll
                for (int j = 0; j < 2; j++) {
                    int col = wn * 32 + nt * 8 + 2 * q + j;
                    float dist = scsq[col] - 2.0f * acc[mt][nt][half * 2 + j];
                    if (dist < bd) { bd = dist; bi = col; }
                }
#pragma unroll
            for (int o = 1; o <= 2; o <<= 1) {
                float od = __shfl_xor_sync(0xffffffffu, bd, o);
                int   oi = __shfl_xor_sync(0xffffffffu, bi, o);
                if (od < bd || (od == bd && oi < bi)) { bd = od; bi = oi; }
            }
            if (q == 0) {
                int lr = wm * 64 + mt * 16 + hr + half * 8;
                sdist[lr][wn] = bd;
                sidx[lr][wn] = bi;
            }
        }
    __syncthreads();
    if (tid < TM) {
        float bd = sdist[tid][0];
        int   bi = sidx[tid][0];
#pragma unroll
        for (int s = 1; s < 4; s++) {
            float od = sdist[tid][s];
            int   oi = sidx[tid][s];
            if (od < bd || (od == bd && oi < bi)) { bd = od; bi = oi; }
        }
        g_bd8[blockIdx.y][row0 + tid] = bd;
        g_bi8[blockIdx.y][row0 + tid] = nbase + bi;
    }
}

// ---------------- fused combine(8 splits) + per-chunk histogram ----------------
__global__ void histo_kernel() {
    __shared__ int h[Kk];
    int c = blockIdx.x;
    int t = threadIdx.x;
#pragma unroll
    for (int i = t; i < Kk; i += CHUNK) h[i] = 0;
    __syncthreads();
    int i = c * CHUNK + t;
    float bd = g_bd8[0][i];
    int   bi = g_bi8[0][i];
#pragma unroll
    for (int s = 1; s < 8; s++) {
        float d = g_bd8[s][i];
        if (d < bd) { bd = d; bi = g_bi8[s][i]; }
    }
    g_asg[i] = bi;
    atomicAdd(&h[bi], 1);
    __syncthreads();
#pragma unroll
    for (int j = t; j < Kk; j += CHUNK) g_hist[c * Kk + j] = h[j];
}

__global__ void scan_kernel() {
    __shared__ int s[Kk];
    int t = threadIdx.x;
    int total = 0;
    for (int c = 0; c < NCHUNK; c++) total += g_hist[c * Kk + t];
    g_counts[t] = total;
    s[t] = total;
    __syncthreads();
    for (int o = 1; o < Kk; o <<= 1) {
        int v = (t >= o) ? s[t - o] : 0;
        __syncthreads();
        s[t] += v;
        __syncthreads();
    }
    int excl = (t == 0) ? 0 : s[t - 1];
    g_offsets[t] = excl;
    int run = excl;
    for (int c = 0; c < NCHUNK; c++) {
        int h = g_hist[c * Kk + t];
        g_hist[c * Kk + t] = run;
        run += h;
    }
}

__global__ void scatter_kernel() {
    __shared__ int ka[CHUNK];
    int c = blockIdx.x;
    int t = threadIdx.x;
    int i = c * CHUNK + t;
    int k = g_asg[i];
    ka[t] = k;
    __syncthreads();
    int rank = 0;
    for (int j = 0; j < t; j++) rank += (ka[j] == k);
    g_order[g_hist[c * Kk + k] + rank] = i;
}

__global__ void update_kernel(const float* __restrict__ feats) {
    int k = blockIdx.x;
    int cnt = g_counts[k];
    if (cnt == 0) return;
    int start = g_offsets[k];
    float inv = 1.0f / (float)cnt;
    for (int d = threadIdx.x; d < Dd; d += blockDim.x) {
        float s = 0.f;
        for (int j = 0; j < cnt; j++)
            s += feats[(size_t)g_order[start + j] * Dd + d];
        g_cent[(size_t)k * Dd + d] = s * (float)cnt * inv * inv;
    }
}

__global__ void dists_kernel(const float* __restrict__ feats) {
    int k = blockIdx.x;
    int cnt = g_counts[k];
    int start = g_offsets[k];
    for (int d = threadIdx.x; d < Dd; d += blockDim.x) {
        float c = g_cent[(size_t)k * Dd + d];
        float s = 0.f;
        for (int j = 0; j < cnt; j++) {
            float r = feats[(size_t)g_order[start + j] * Dd + d] - c;
            s = fmaf(r, r, s);
        }
        g_dists[(size_t)k * Dd + d] = s;
    }
}

__global__ void reduce1_kernel() {
    double s = 0.0;
    int stride = gridDim.x * blockDim.x;
    for (int i = blockIdx.x * blockDim.x + threadIdx.x; i < Kk * Dd; i += stride)
        s += (double)expf(-g_dists[i] / CONCENTRATION);
    __shared__ double sm[256];
    sm[threadIdx.x] = s;
    __syncthreads();
    for (int o = 128; o; o >>= 1) {
        if (threadIdx.x < o) sm[threadIdx.x] += sm[threadIdx.x + o];
        __syncthreads();
    }
    if (threadIdx.x == 0) g_part1[blockIdx.x] = sm[0];
}

__global__ void finalize1_kernel() {
    __shared__ double sm[256];
    sm[threadIdx.x] = g_part1[threadIdx.x];
    __syncthreads();
    for (int o = 128; o; o >>= 1) {
        if (threadIdx.x < o) sm[threadIdx.x] += sm[threadIdx.x + o];
        __syncthreads();
    }
    if (threadIdx.x == 0) g_S = sm[0];
}

__global__ void reduce2_kernel() {
    float Sf = (float)g_S;
    double e1 = 0.0, e2 = 0.0;
    int stride = gridDim.x * blockDim.x;
    for (int i = blockIdx.x * blockDim.x + threadIdx.x; i < Kk * Dd; i += stride) {
        float dv = g_dists[i];
        float p  = expf(-dv / CONCENTRATION);
        float q  = p / Sf;
        e1 += (double)(q * logf(q + EPSf));
        float p2 = expf(-dv / TEMPERATURE);
        e2 += (double)logf(p2 + EPSf);
    }
    __shared__ double sa[256], sb[256];
    sa[threadIdx.x] = e1;
    sb[threadIdx.x] = e2;
    __syncthreads();
    for (int o = 128; o; o >>= 1) {
        if (threadIdx.x < o) {
            sa[threadIdx.x] += sa[threadIdx.x + o];
            sb[threadIdx.x] += sb[threadIdx.x + o];
        }
        __syncthreads();
    }
    if (threadIdx.x == 0) {
        g_part2a[blockIdx.x] = sa[0];
        g_part2b[blockIdx.x] = sb[0];
    }
}

__global__ void finalize2_kernel(float* __restrict__ out) {
    __shared__ double sa[256], sb[256];
    sa[threadIdx.x] = g_part2a[threadIdx.x];
    sb[threadIdx.x] = g_part2b[threadIdx.x];
    __syncthreads();
    for (int o = 128; o; o >>= 1) {
        if (threadIdx.x < o) {
            sa[threadIdx.x] += sa[threadIdx.x + o];
            sb[threadIdx.x] += sb[threadIdx.x + o];
        }
        __syncthreads();
    }
    if (threadIdx.x == 0) {
        double kd = (double)(Kk * Dd);
        double entropy = (sa[0] / kd);
        double nll = -(sb[0] / kd);
        out[0] = (float)(entropy + nll);
    }
}

extern "C" void kernel_launch(void* const* d_in, const int* in_sizes, int n_in,
                              void* d_out, int out_size) {
    const float* feats = (const float*)d_in[0];
    float* out = (float*)d_out;
    (void)in_sizes; (void)n_in; (void)out_size;

    static bool attr_done = false;
    if (!attr_done) {
        cudaFuncSetAttribute(assign_mma_kernel,
                             cudaFuncAttributeMaxDynamicSharedMemorySize, SMEM_BYTES);
        attr_done = true;
    }

    dim3 agrid(Nn / TM, Kk / TN);

    copy_init_kernel<<<(Kk * Dd + 255) / 256, 256>>>(feats);
    split_feats_kernel<<<(Nn * Dd + 255) / 256, 256>>>(feats);

    for (int it = 0; it < NUM_ITERS; it++) {
        split_csq_kernel<<<(Kk * 32) / 256, 256>>>();
        assign_mma_kernel<<<agrid, 256, SMEM_BYTES>>>();
        histo_kernel<<<NCHUNK, CHUNK>>>();
        scan_kernel<<<1, Kk>>>();
        scatter_kernel<<<NCHUNK, CHUNK>>>();
        update_kernel<<<Kk, 128>>>(feats);
    }

    split_csq_kernel<<<(Kk * 32) / 256, 256>>>();
    assign_mma_kernel<<<agrid, 256, SMEM_BYTES>>>();
    histo_kernel<<<NCHUNK, CHUNK>>>();
    scan_kernel<<<1, Kk>>>();
    scatter_kernel<<<NCHUNK, CHUNK>>>();
    dists_kernel<<<Kk, 128>>>(feats);

    reduce1_kernel<<<256, 256>>>();
    finalize1_kernel<<<1, 256>>>();
    reduce2_kernel<<<256, 256>>>();
    finalize2_kernel<<<1, 256>>>(out);
}

// round 15
// speedup vs baseline: 1.0054x; 1.0054x over previous
#include <cuda_runtime.h>
#include <cuda_fp16.h>
#include <math.h>
#include <stdint.h>

#define Nn 16384
#define Dd 512
#define Kk 1024
#define NUM_ITERS 10
#define TEMPERATURE 0.1f
#define CONCENTRATION 0.1f
#define EPSf 1e-6f

#define NCHUNK 64
#define CHUNK  256

// ---------------- device scratch ----------------
__device__ float  g_cent[Kk * Dd];
__device__ float  g_csq[Kk];
__device__ __align__(16) __half g_fh[Nn * Dd];   // feats fp16 hi
__device__ __align__(16) __half g_fm[Nn * Dd];   // feats fp16 lo
__device__ __align__(16) __half g_ch[Kk * Dd];   // centroid fp16 hi
__device__ __align__(16) __half g_cm[Kk * Dd];   // centroid fp16 lo
__device__ int    g_asg[Nn];
__device__ float  g_bd8[8][Nn];
__device__ int    g_bi8[8][Nn];
__device__ int    g_counts[Kk];
__device__ int    g_offsets[Kk];
__device__ int    g_hist[NCHUNK * Kk];
__device__ int    g_order[Nn];
__device__ float  g_dists[Kk * Dd];
__device__ double g_part1[256];
__device__ double g_part2a[256];
__device__ double g_part2b[256];
__device__ double g_S;

__global__ void copy_init_kernel(const float* __restrict__ feats) {
    int i = blockIdx.x * blockDim.x + threadIdx.x;
    if (i < Kk * Dd) g_cent[i] = feats[i];
}

__global__ void split_feats_kernel(const float* __restrict__ feats) {
    int i = blockIdx.x * blockDim.x + threadIdx.x;
    if (i >= Nn * Dd) return;
    float x = feats[i];
    __half h = __float2half_rn(x);
    __half m = __float2half_rn(x - __half2float(h));
    g_fh[i] = h;
    g_fm[i] = m;
}

// fused: centroid fp16 split + squared norms (warp per centroid row)
__global__ void split_csq_kernel() {
    int warp = (blockIdx.x * blockDim.x + threadIdx.x) >> 5;
    int lane = threadIdx.x & 31;
    if (warp >= Kk) return;
    const float2* r = (const float2*)(g_cent + (size_t)warp * Dd);
    __half2* ch2 = (__half2*)(g_ch + (size_t)warp * Dd);
    __half2* cm2 = (__half2*)(g_cm + (size_t)warp * Dd);
    float s = 0.f;
#pragma unroll
    for (int i = 0; i < Dd / 64; i++) {
        float2 v = r[lane + i * 32];
        __half hx = __float2half_rn(v.x), hy = __float2half_rn(v.y);
        __half mx = __float2half_rn(v.x - __half2float(hx));
        __half my = __float2half_rn(v.y - __half2float(hy));
        ch2[lane + i * 32] = __halves2half2(hx, hy);
        cm2[lane + i * 32] = __halves2half2(mx, my);
        s += v.x * v.x + v.y * v.y;
    }
#pragma unroll
    for (int o = 16; o; o >>= 1) s += __shfl_xor_sync(0xffffffffu, s, o);
    if (lane == 0) g_csq[warp] = s;
}

// ================= mma.sync (HMMA) assignment =================
// Block: 128 points x 128 clusters; grid (128, 8 N-splits); 256 threads.
// dot = xh*ch + xh*cm + xm*ch in fp32 via m16n8k16 fp16 mma.
// KC=32 chunks, 3-stage cp.async pipeline, 96KB dynamic smem -> 2 blocks/SM.
#define TM 128
#define TN 128
#define KC 32                  // halves per d-chunk
#define NCHK2 (Dd / KC)        // 16

// per-stage: rows of 32 halves = 64B = 4x16B granules
#define OFF_AH 0
#define OFF_AM (TM * KC * 2)                   // 8192
#define OFF_BH (2 * TM * KC * 2)               // 16384
#define OFF_BM (2 * TM * KC * 2 + TN * KC * 2) // 24576
#define STAGE_BYTES (2 * TM * KC * 2 + 2 * TN * KC * 2)  // 32768
#define SMEM_BYTES (3 * STAGE_BYTES)                     // 98304

// swizzled byte offset for (row, 16B-granule), 4 granules per 64B row
#define SWZ32(row_, grp_) ((uint32_t)((((row_) << 2) + ((grp_) ^ (((row_) >> 1) & 3))) * 16))

__device__ __forceinline__ uint32_t smem_u32(const void* p) {
    uint32_t a;
    asm("{ .reg .u64 t; cvta.to.shared.u64 t, %1; cvt.u32.u64 %0, t; }" : "=r"(a) : "l"(p));
    return a;
}

__device__ __forceinline__ void cp16(uint32_t saddr, const void* gptr) {
    asm volatile("cp.async.cg.shared.global [%0], [%1], 16;"
                 :: "r"(saddr), "l"(gptr) : "memory");
}

__device__ __forceinline__ void ldsm_x4(uint32_t addr, uint32_t& r0, uint32_t& r1,
                                        uint32_t& r2, uint32_t& r3) {
    asm volatile("ldmatrix.sync.aligned.m8n8.x4.shared.b16 {%0,%1,%2,%3}, [%4];"
                 : "=r"(r0), "=r"(r1), "=r"(r2), "=r"(r3) : "r"(addr));
}

__device__ __forceinline__ void mma16816(float* d, const uint32_t* a, const uint32_t* b) {
    asm volatile(
        "mma.sync.aligned.m16n8k16.row.col.f32.f16.f16.f32 "
        "{%0,%1,%2,%3}, {%4,%5,%6,%7}, {%8,%9}, {%0,%1,%2,%3};"
        : "+f"(d[0]), "+f"(d[1]), "+f"(d[2]), "+f"(d[3])
        : "r"(a[0]), "r"(a[1]), "r"(a[2]), "r"(a[3]), "r"(b[0]), "r"(b[1]));
}

extern __shared__ char dsm[];

__global__ void __launch_bounds__(256, 2) assign_mma_kernel() {
    __shared__ float scsq[TN];
    __shared__ float sdist[TM][4];
    __shared__ int   sidx[TM][4];

    int tid = threadIdx.x;
    int lane = tid & 31;
    int w = tid >> 5;
    int wm = w >> 2, wn = w & 3;           // warp grid 2 x 4
    int row0 = blockIdx.x * TM;
    int nbase = blockIdx.y * TN;

    uint32_t sb = smem_u32(dsm);

    if (tid < TN) scsq[tid] = g_csq[nbase + tid];

    float acc[4][4][4];
#pragma unroll
    for (int mt = 0; mt < 4; mt++)
#pragma unroll
        for (int nt = 0; nt < 4; nt++)
#pragma unroll
            for (int r = 0; r < 4; r++) acc[mt][nt][r] = 0.f;

#define ISSUE_CHUNK(ch_, stg_)                                                     \
    do {                                                                           \
        int d0_ = (ch_) * KC;                                                      \
        uint32_t sbase_ = sb + (stg_) * STAGE_BYTES;                               \
        _Pragma("unroll")                                                          \
        for (int u_ = 0; u_ < 2; u_++) {                                           \
            int idx_ = tid + u_ * 256;                                             \
            int row_ = idx_ >> 2, grp_ = idx_ & 3;                                 \
            uint32_t so_ = SWZ32(row_, grp_);                                      \
            size_t goff_ = (size_t)row_ * Dd + d0_ + grp_ * 8;                     \
            cp16(sbase_ + OFF_AH + so_, g_fh + (size_t)row0 * Dd + goff_);         \
            cp16(sbase_ + OFF_AM + so_, g_fm + (size_t)row0 * Dd + goff_);         \
            cp16(sbase_ + OFF_BH + so_, g_ch + (size_t)nbase * Dd + goff_);        \
            cp16(sbase_ + OFF_BM + so_, g_cm + (size_t)nbase * Dd + goff_);        \
        }                                                                          \
        asm volatile("cp.async.commit_group;" ::: "memory");                       \
    } while (0)

    // ldmatrix address components
    int arow_b = wm * 64 + (lane & 7) + ((lane >> 3) & 1) * 8;   // + mt*16
    int agrp_h = (lane >> 4);                                    // + ks*2
    int brow_b = wn * 32 + (lane & 7) + ((lane >> 4) << 3);      // + bt*16
    int bgrp_h = ((lane >> 3) & 1);

    ISSUE_CHUNK(0, 0);
    ISSUE_CHUNK(1, 1);

    for (int ch2 = 0; ch2 < NCHK2; ch2++) {
        int stg = ch2 % 3;
        if (ch2 + 2 < NCHK2) {
            ISSUE_CHUNK(ch2 + 2, (ch2 + 2) % 3);
            asm volatile("cp.async.wait_group 2;" ::: "memory");
        } else if (ch2 + 1 < NCHK2) {
            asm volatile("cp.async.wait_group 1;" ::: "memory");
        } else {
            asm volatile("cp.async.wait_group 0;" ::: "memory");
        }
        __syncthreads();

        uint32_t sbase = sb + stg * STAGE_BYTES;
#pragma unroll
        for (int ks = 0; ks < KC / 16; ks++) {
            uint32_t ah[4][4], am[4][4];
#pragma unroll
            for (int mt = 0; mt < 4; mt++) {
                int row = arow_b + mt * 16;
                int grp = ks * 2 + agrp_h;
                uint32_t so = SWZ32(row, grp);
                ldsm_x4(sbase + OFF_AH + so, ah[mt][0], ah[mt][1], ah[mt][2], ah[mt][3]);
                ldsm_x4(sbase + OFF_AM + so, am[mt][0], am[mt][1], am[mt][2], am[mt][3]);
            }
#pragma unroll
            for (int bt = 0; bt < 2; bt++) {
                uint32_t bh[4], bm[4];
                int row = brow_b + bt * 16;
                int grp = ks * 2 + bgrp_h;
                uint32_t so = SWZ32(row, grp);
                ldsm_x4(sbase + OFF_BH + so, bh[0], bh[1], bh[2], bh[3]);
                ldsm_x4(sbase + OFF_BM + so, bm[0], bm[1], bm[2], bm[3]);
#pragma unroll
                for (int n2 = 0; n2 < 2; n2++) {
                    int nt = bt * 2 + n2;
#pragma unroll
                    for (int mt = 0; mt < 4; mt++) {
                        mma16816(acc[mt][nt], ah[mt], bh + 2 * n2);   // hh
                        mma16816(acc[mt][nt], ah[mt], bm + 2 * n2);   // hm
                        mma16816(acc[mt][nt], am[mt], bh + 2 * n2);   // mh
                    }
                }
            }
        }
        __syncthreads();
    }

    // ---------------- epilogue: distances + argmin ----------------
    int q = lane & 3, hr = lane >> 2;
#pragma unroll
    for (int mt = 0; mt < 4; mt++)
#pragma unroll
        for (int half = 0; half < 2; half++) {
            float bd = 3.4e38f;
            int bi = 0;
#pragma unroll
            for (int nt = 0; nt < 4; nt++)
#pragma unroll
                for (int j = 0; j < 2; j++) {
                    int col = wn * 32 + nt * 8 + 2 * q + j;
                    float dist = scsq[col] - 2.0f * acc[mt][nt][half * 2 + j];
                    if (dist < bd) { bd = dist; bi = col; }
                }
#pragma unroll
            for (int o = 1; o <= 2; o <<= 1) {
                float od = __shfl_xor_sync(0xffffffffu, bd, o);
                int   oi = __shfl_xor_sync(0xffffffffu, bi, o);
                if (od < bd || (od == bd && oi < bi)) { bd = od; bi = oi; }
            }
            if (q == 0) {
                int lr = wm * 64 + mt * 16 + hr + half * 8;
                sdist[lr][wn] = bd;
                sidx[lr][wn] = bi;
            }
        }
    __syncthreads();
    if (tid < TM) {
        float bd = sdist[tid][0];
        int   bi = sidx[tid][0];
#pragma unroll
        for (int s = 1; s < 4; s++) {
            float od = sdist[tid][s];
            int   oi = sidx[tid][s];
            if (od < bd || (od == bd && oi < bi)) { bd = od; bi = oi; }
        }
        g_bd8[blockIdx.y][row0 + tid] = bd;
        g_bi8[blockIdx.y][row0 + tid] = nbase + bi;
    }
}

// ---------------- fused combine(8 splits) + per-chunk histogram ----------------
__global__ void histo_kernel() {
    __shared__ int h[Kk];
    int c = blockIdx.x;
    int t = threadIdx.x;
#pragma unroll
    for (int i = t; i < Kk; i += CHUNK) h[i] = 0;
    __syncthreads();
    int i = c * CHUNK + t;
    float bd = g_bd8[0][i];
    int   bi = g_bi8[0][i];
#pragma unroll
    for (int s = 1; s < 8; s++) {
        float d = g_bd8[s][i];
        if (d < bd) { bd = d; bi = g_bi8[s][i]; }
    }
    g_asg[i] = bi;
    atomicAdd(&h[bi], 1);
    __syncthreads();
#pragma unroll
    for (int j = t; j < Kk; j += CHUNK) g_hist[c * Kk + j] = h[j];
}

__global__ void scan_kernel() {
    __shared__ int s[Kk];
    int t = threadIdx.x;
    int total = 0;
    for (int c = 0; c < NCHUNK; c++) total += g_hist[c * Kk + t];
    g_counts[t] = total;
    s[t] = total;
    __syncthreads();
    for (int o = 1; o < Kk; o <<= 1) {
        int v = (t >= o) ? s[t - o] : 0;
        __syncthreads();
        s[t] += v;
        __syncthreads();
    }
    int excl = (t == 0) ? 0 : s[t - 1];
    g_offsets[t] = excl;
    int run = excl;
    for (int c = 0; c < NCHUNK; c++) {
        int h = g_hist[c * Kk + t];
        g_hist[c * Kk + t] = run;
        run += h;
    }
}

__global__ void scatter_kernel() {
    __shared__ int ka[CHUNK];
    int c = blockIdx.x;
    int t = threadIdx.x;
    int i = c * CHUNK + t;
    int k = g_asg[i];
    ka[t] = k;
    __syncthreads();
    int rank = 0;
    for (int j = 0; j < t; j++) rank += (ka[j] == k);
    g_order[g_hist[c * Kk + k] + rank] = i;
}

__global__ void update_kernel(const float* __restrict__ feats) {
    int k = blockIdx.x;
    int cnt = g_counts[k];
    if (cnt == 0) return;
    int start = g_offsets[k];
    float inv = 1.0f / (float)cnt;
    for (int d = threadIdx.x; d < Dd; d += blockDim.x) {
        float s = 0.f;
        for (int j = 0; j < cnt; j++)
            s += feats[(size_t)g_order[start + j] * Dd + d];
        g_cent[(size_t)k * Dd + d] = s * (float)cnt * inv * inv;
    }
}

__global__ void dists_kernel(const float* __restrict__ feats) {
    int k = blockIdx.x;
    int cnt = g_counts[k];
    int start = g_offsets[k];
    for (int d = threadIdx.x; d < Dd; d += blockDim.x) {
        float c = g_cent[(size_t)k * Dd + d];
        float s = 0.f;
        for (int j = 0; j < cnt; j++) {
            float r = feats[(size_t)g_order[start + j] * Dd + d] - c;
            s = fmaf(r, r, s);
        }
        g_dists[(size_t)k * Dd + d] = s;
    }
}

__global__ void reduce1_kernel() {
    double s = 0.0;
    int stride = gridDim.x * blockDim.x;
    for (int i = blockIdx.x * blockDim.x + threadIdx.x; i < Kk * Dd; i += stride)
        s += (double)expf(-g_dists[i] / CONCENTRATION);
    __shared__ double sm[256];
    sm[threadIdx.x] = s;
    __syncthreads();
    for (int o = 128; o; o >>= 1) {
        if (threadIdx.x < o) sm[threadIdx.x] += sm[threadIdx.x + o];
        __syncthreads();
    }
    if (threadIdx.x == 0) g_part1[blockIdx.x] = sm[0];
}

__global__ void finalize1_kernel() {
    __shared__ double sm[256];
    sm[threadIdx.x] = g_part1[threadIdx.x];
    __syncthreads();
    for (int o = 128; o; o >>= 1) {
        if (threadIdx.x < o) sm[threadIdx.x] += sm[threadIdx.x + o];
        __syncthreads();
    }
    if (threadIdx.x == 0) g_S = sm[0];
}

__global__ void reduce2_kernel() {
    float Sf = (float)g_S;
    double e1 = 0.0, e2 = 0.0;
    int stride = gridDim.x * blockDim.x;
    for (int i = blockIdx.x * blockDim.x + threadIdx.x; i < Kk * Dd; i += stride) {
        float dv = g_dists[i];
        float p  = expf(-dv / CONCENTRATION);
        float q  = p / Sf;
        e1 += (double)(q * logf(q + EPSf));
        float p2 = expf(-dv / TEMPERATURE);
        e2 += (double)logf(p2 + EPSf);
    }
    __shared__ double sa[256], sb[256];
    sa[threadIdx.x] = e1;
    sb[threadIdx.x] = e2;
    __syncthreads();
    for (int o = 128; o; o >>= 1) {
        if (threadIdx.x < o) {
            sa[threadIdx.x] += sa[threadIdx.x + o];
            sb[threadIdx.x] += sb[threadIdx.x + o];
        }
        __syncthreads();
    }
    if (threadIdx.x == 0) {
        g_part2a[blockIdx.x] = sa[0];
        g_part2b[blockIdx.x] = sb[0];
    }
}

__global__ void finalize2_kernel(float* __restrict__ out) {
    __shared__ double sa[256], sb[256];
    sa[threadIdx.x] = g_part2a[threadIdx.x];
    sb[threadIdx.x] = g_part2b[threadIdx.x];
    __syncthreads();
    for (int o = 128; o; o >>= 1) {
        if (threadIdx.x < o) {
            sa[threadIdx.x] += sa[threadIdx.x + o];
            sb[threadIdx.x] += sb[threadIdx.x + o];
        }
        __syncthreads();
    }
    if (threadIdx.x == 0) {
        double kd = (double)(Kk * Dd);
        double entropy = (sa[0] / kd);
        double nll = -(sb[0] / kd);
        out[0] = (float)(entropy + nll);
    }
}

extern "C" void kernel_launch(void* const* d_in, const int* in_sizes, int n_in,
                              void* d_out, int out_size) {
    const float* feats = (const float*)d_in[0];
    float* out = (float*)d_out;
    (void)in_sizes; (void)n_in; (void)out_size;

    static bool attr_done = false;
    if (!attr_done) {
        cudaFuncSetAttribute(assign_mma_kernel,
                             cudaFuncAttributeMaxDynamicSharedMemorySize, SMEM_BYTES);
        attr_done = true;
    }

    dim3 agrid(Nn / TM, Kk / TN);

    copy_init_kernel<<<(Kk * Dd + 255) / 256, 256>>>(feats);
    split_feats_kernel<<<(Nn * Dd + 255) / 256, 256>>>(feats);

    for (int it = 0; it < NUM_ITERS; it++) {
        split_csq_kernel<<<(Kk * 32) / 256, 256>>>();
        assign_mma_kernel<<<agrid, 256, SMEM_BYTES>>>();
        histo_kernel<<<NCHUNK, CHUNK>>>();
        scan_kernel<<<1, Kk>>>();
        scatter_kernel<<<NCHUNK, CHUNK>>>();
        update_kernel<<<Kk, 128>>>(feats);
    }

    split_csq_kernel<<<(Kk * 32) / 256, 256>>>();
    assign_mma_kernel<<<agrid, 256, SMEM_BYTES>>>();
    histo_kernel<<<NCHUNK, CHUNK>>>();
    scan_kernel<<<1, Kk>>>();
    scatter_kernel<<<NCHUNK, CHUNK>>>();
    dists_kernel<<<Kk, 128>>>(feats);

    reduce1_kernel<<<256, 256>>>();
    finalize1_kernel<<<1, 256>>>();
    reduce2_kernel<<<256, 256>>>();
    finalize2_kernel<<<1, 256>>>(out);
}

// round 16
// speedup vs baseline: 1.5217x; 1.5134x over previous
#include <cuda_runtime.h>
#include <cuda_fp16.h>
#include <math.h>
#include <stdint.h>

#define Nn 16384
#define Dd 512
#define Kk 1024
#define NUM_ITERS 10
#define TEMPERATURE 0.1f
#define CONCENTRATION 0.1f
#define EPSf 1e-6f

#define NCHUNK 64
#define CHUNK  256

// ---------------- device scratch ----------------
__device__ float  g_cent[Kk * Dd];
__device__ float  g_csq[Kk];
__device__ __align__(16) __half g_fh[Nn * Dd];   // feats fp16 hi
__device__ __align__(16) __half g_fm[Nn * Dd];   // feats fp16 lo
__device__ __align__(16) __half g_ch[Kk * Dd];   // centroid fp16 hi
__device__ __align__(16) __half g_cm[Kk * Dd];   // centroid fp16 lo
__device__ int    g_asg[Nn];
__device__ float  g_bd8[8][Nn];
__device__ int    g_bi8[8][Nn];
__device__ int    g_counts[Kk];
__device__ int    g_offsets[Kk];
__device__ int    g_hist[NCHUNK * Kk];
__device__ int    g_order[Nn];
__device__ float  g_dists[Kk * Dd];
__device__ double g_part1[256];
__device__ double g_part2a[256];
__device__ double g_part2b[256];
__device__ double g_S;

__global__ void copy_init_kernel(const float* __restrict__ feats) {
    int i = blockIdx.x * blockDim.x + threadIdx.x;
    if (i < Kk * Dd) g_cent[i] = feats[i];
}

__global__ void split_feats_kernel(const float* __restrict__ feats) {
    int i = blockIdx.x * blockDim.x + threadIdx.x;
    if (i >= Nn * Dd) return;
    float x = feats[i];
    __half h = __float2half_rn(x);
    __half m = __float2half_rn(x - __half2float(h));
    g_fh[i] = h;
    g_fm[i] = m;
}

// fused: centroid fp16 split + squared norms (warp per centroid row)
__global__ void split_csq_kernel() {
    int warp = (blockIdx.x * blockDim.x + threadIdx.x) >> 5;
    int lane = threadIdx.x & 31;
    if (warp >= Kk) return;
    const float2* r = (const float2*)(g_cent + (size_t)warp * Dd);
    __half2* ch2 = (__half2*)(g_ch + (size_t)warp * Dd);
    __half2* cm2 = (__half2*)(g_cm + (size_t)warp * Dd);
    float s = 0.f;
#pragma unroll
    for (int i = 0; i < Dd / 64; i++) {
        float2 v = r[lane + i * 32];
        __half hx = __float2half_rn(v.x), hy = __float2half_rn(v.y);
        __half mx = __float2half_rn(v.x - __half2float(hx));
        __half my = __float2half_rn(v.y - __half2float(hy));
        ch2[lane + i * 32] = __halves2half2(hx, hy);
        cm2[lane + i * 32] = __halves2half2(mx, my);
        s += v.x * v.x + v.y * v.y;
    }
#pragma unroll
    for (int o = 16; o; o >>= 1) s += __shfl_xor_sync(0xffffffffu, s, o);
    if (lane == 0) g_csq[warp] = s;
}

// ================= mma.sync (HMMA) assignment =================
// Block: 128 points x 128 clusters; grid (128, 8 N-splits); 256 threads.
// dot = xh*ch + xh*cm + xm*ch in fp32 via m16n8k16 fp16 mma.
// KC=32 chunks, 3-stage cp.async pipeline, 96KB dynamic smem -> 2 blocks/SM.
#define TM 128
#define TN 128
#define KC 32                  // halves per d-chunk
#define NCHK2 (Dd / KC)        // 16

// per-stage: rows of 32 halves = 64B = 4x16B granules
#define OFF_AH 0
#define OFF_AM (TM * KC * 2)                   // 8192
#define OFF_BH (2 * TM * KC * 2)               // 16384
#define OFF_BM (2 * TM * KC * 2 + TN * KC * 2) // 24576
#define STAGE_BYTES (2 * TM * KC * 2 + 2 * TN * KC * 2)  // 32768
#define SMEM_BYTES (3 * STAGE_BYTES)                     // 98304

// swizzled byte offset for (row, 16B-granule), 4 granules per 64B row
#define SWZ32(row_, grp_) ((uint32_t)((((row_) << 2) + ((grp_) ^ (((row_) >> 1) & 3))) * 16))

__device__ __forceinline__ uint32_t smem_u32(const void* p) {
    uint32_t a;
    asm("{ .reg .u64 t; cvta.to.shared.u64 t, %1; cvt.u32.u64 %0, t; }" : "=r"(a) : "l"(p));
    return a;
}

__device__ __forceinline__ void cp16(uint32_t saddr, const void* gptr) {
    asm volatile("cp.async.cg.shared.global [%0], [%1], 16;"
                 :: "r"(saddr), "l"(gptr) : "memory");
}

__device__ __forceinline__ void ldsm_x4(uint32_t addr, uint32_t& r0, uint32_t& r1,
                                        uint32_t& r2, uint32_t& r3) {
    asm volatile("ldmatrix.sync.aligned.m8n8.x4.shared.b16 {%0,%1,%2,%3}, [%4];"
                 : "=r"(r0), "=r"(r1), "=r"(r2), "=r"(r3) : "r"(addr));
}

__device__ __forceinline__ void mma16816(float* d, const uint32_t* a, const uint32_t* b) {
    asm volatile(
        "mma.sync.aligned.m16n8k16.row.col.f32.f16.f16.f32 "
        "{%0,%1,%2,%3}, {%4,%5,%6,%7}, {%8,%9}, {%0,%1,%2,%3};"
        : "+f"(d[0]), "+f"(d[1]), "+f"(d[2]), "+f"(d[3])
        : "r"(a[0]), "r"(a[1]), "r"(a[2]), "r"(a[3]), "r"(b[0]), "r"(b[1]));
}

extern __shared__ char dsm[];

__global__ void __launch_bounds__(256, 2) assign_mma_kernel() {
    __shared__ float scsq[TN];
    __shared__ float sdist[TM][4];
    __shared__ int   sidx[TM][4];

    int tid = threadIdx.x;
    int lane = tid & 31;
    int w = tid >> 5;
    int wm = w >> 2, wn = w & 3;           // warp grid 2 x 4
    int row0 = blockIdx.x * TM;
    int nbase = blockIdx.y * TN;

    uint32_t sb = smem_u32(dsm);

    if (tid < TN) scsq[tid] = g_csq[nbase + tid];

    float acc[4][4][4];
#pragma unroll
    for (int mt = 0; mt < 4; mt++)
#pragma unroll
        for (int nt = 0; nt < 4; nt++)
#pragma unroll
            for (int r = 0; r < 4; r++) acc[mt][nt][r] = 0.f;

#define ISSUE_CHUNK(ch_, stg_)                                                     \
    do {                                                                           \
        int d0_ = (ch_) * KC;                                                      \
        uint32_t sbase_ = sb + (stg_) * STAGE_BYTES;                               \
        _Pragma("unroll")                                                          \
        for (int u_ = 0; u_ < 2; u_++) {                                           \
            int idx_ = tid + u_ * 256;                                             \
            int row_ = idx_ >> 2, grp_ = idx_ & 3;                                 \
            uint32_t so_ = SWZ32(row_, grp_);                                      \
            size_t goff_ = (size_t)row_ * Dd + d0_ + grp_ * 8;                     \
            cp16(sbase_ + OFF_AH + so_, g_fh + (size_t)row0 * Dd + goff_);         \
            cp16(sbase_ + OFF_AM + so_, g_fm + (size_t)row0 * Dd + goff_);         \
            cp16(sbase_ + OFF_BH + so_, g_ch + (size_t)nbase * Dd + goff_);        \
            cp16(sbase_ + OFF_BM + so_, g_cm + (size_t)nbase * Dd + goff_);        \
        }                                                                          \
        asm volatile("cp.async.commit_group;" ::: "memory");                       \
    } while (0)

    // ldmatrix address components
    int arow_b = wm * 64 + (lane & 7) + ((lane >> 3) & 1) * 8;   // + mt*16
    int agrp_h = (lane >> 4);                                    // + ks*2
    int brow_b = wn * 32 + (lane & 7) + ((lane >> 4) << 3);      // + bt*16
    int bgrp_h = ((lane >> 3) & 1);

    ISSUE_CHUNK(0, 0);
    ISSUE_CHUNK(1, 1);

    for (int ch2 = 0; ch2 < NCHK2; ch2++) {
        int stg = ch2 % 3;
        if (ch2 + 2 < NCHK2) {
            ISSUE_CHUNK(ch2 + 2, (ch2 + 2) % 3);
            asm volatile("cp.async.wait_group 2;" ::: "memory");
        } else if (ch2 + 1 < NCHK2) {
            asm volatile("cp.async.wait_group 1;" ::: "memory");
        } else {
            asm volatile("cp.async.wait_group 0;" ::: "memory");
        }
        __syncthreads();

        uint32_t sbase = sb + stg * STAGE_BYTES;
#pragma unroll
        for (int ks = 0; ks < KC / 16; ks++) {
            uint32_t ah[4][4], am[4][4];
#pragma unroll
            for (int mt = 0; mt < 4; mt++) {
                int row = arow_b + mt * 16;
                int grp = ks * 2 + agrp_h;
                uint32_t so = SWZ32(row, grp);
                ldsm_x4(sbase + OFF_AH + so, ah[mt][0], ah[mt][1], ah[mt][2], ah[mt][3]);
                ldsm_x4(sbase + OFF_AM + so, am[mt][0], am[mt][1], am[mt][2], am[mt][3]);
            }
#pragma unroll
            for (int bt = 0; bt < 2; bt++) {
                uint32_t bh[4], bm[4];
                int row = brow_b + bt * 16;
                int grp = ks * 2 + bgrp_h;
                uint32_t so = SWZ32(row, grp);
                ldsm_x4(sbase + OFF_BH + so, bh[0], bh[1], bh[2], bh[3]);
                ldsm_x4(sbase + OFF_BM + so, bm[0], bm[1], bm[2], bm[3]);
#pragma unroll
                for (int n2 = 0; n2 < 2; n2++) {
                    int nt = bt * 2 + n2;
#pragma unroll
                    for (int mt = 0; mt < 4; mt++) {
                        mma16816(acc[mt][nt], ah[mt], bh + 2 * n2);   // hh
                        mma16816(acc[mt][nt], ah[mt], bm + 2 * n2);   // hm
                        mma16816(acc[mt][nt], am[mt], bh + 2 * n2);   // mh
                    }
                }
            }
        }
        __syncthreads();
    }

    // ---------------- epilogue: distances + argmin ----------------
    int q = lane & 3, hr = lane >> 2;
#pragma unroll
    for (int mt = 0; mt < 4; mt++)
#pragma unroll
        for (int half = 0; half < 2; half++) {
            float bd = 3.4e38f;
            int bi = 0;
#pragma unroll
            for (int nt = 0; nt < 4; nt++)
#pragma unroll
                for (int j = 0; j < 2; j++) {
                    int col = wn * 32 + nt * 8 + 2 * q + j;
                    float dist = scsq[col] - 2.0f * acc[mt][nt][half * 2 + j];
                    if (dist < bd) { bd = dist; bi = col; }
                }
#pragma unroll
            for (int o = 1; o <= 2; o <<= 1) {
                float od = __shfl_xor_sync(0xffffffffu, bd, o);
                int   oi = __shfl_xor_sync(0xffffffffu, bi, o);
                if (od < bd || (od == bd && oi < bi)) { bd = od; bi = oi; }
            }
            if (q == 0) {
                int lr = wm * 64 + mt * 16 + hr + half * 8;
                sdist[lr][wn] = bd;
                sidx[lr][wn] = bi;
            }
        }
    __syncthreads();
    if (tid < TM) {
        float bd = sdist[tid][0];
        int   bi = sidx[tid][0];
#pragma unroll
        for (int s = 1; s < 4; s++) {
            float od = sdist[tid][s];
            int   oi = sidx[tid][s];
            if (od < bd || (od == bd && oi < bi)) { bd = od; bi = oi; }
        }
        g_bd8[blockIdx.y][row0 + tid] = bd;
        g_bi8[blockIdx.y][row0 + tid] = nbase + bi;
    }
}

// ---------------- fused combine(8 splits) + per-chunk histogram ----------------
__global__ void histo_kernel() {
    __shared__ int h[Kk];
    int c = blockIdx.x;
    int t = threadIdx.x;
#pragma unroll
    for (int i = t; i < Kk; i += CHUNK) h[i] = 0;
    __syncthreads();
    int i = c * CHUNK + t;
    float bd = g_bd8[0][i];
    int   bi = g_bi8[0][i];
#pragma unroll
    for (int s = 1; s < 8; s++) {
        float d = g_bd8[s][i];
        if (d < bd) { bd = d; bi = g_bi8[s][i]; }
    }
    g_asg[i] = bi;
    atomicAdd(&h[bi], 1);
    __syncthreads();
#pragma unroll
    for (int j = t; j < Kk; j += CHUNK) g_hist[c * Kk + j] = h[j];
}

// counts + exclusive offsets (single block; reduced workload)
__global__ void scan_kernel() {
    __shared__ int s[Kk];
    int t = threadIdx.x;
    int total = 0;
    for (int c = 0; c < NCHUNK; c++) total += g_hist[c * Kk + t];
    g_counts[t] = total;
    s[t] = total;
    __syncthreads();
    for (int o = 1; o < Kk; o <<= 1) {
        int v = (t >= o) ? s[t - o] : 0;
        __syncthreads();
        s[t] += v;
        __syncthreads();
    }
    g_offsets[t] = (t == 0) ? 0 : s[t - 1];
}

// per-cluster chunk-base rewrite, spread over 8 blocks for latency hiding
__global__ void bases_kernel() {
    int t = blockIdx.x * blockDim.x + threadIdx.x;   // cluster id
    int run = g_offsets[t];
    for (int c = 0; c < NCHUNK; c++) {
        int h = g_hist[c * Kk + t];
        g_hist[c * Kk + t] = run;
        run += h;
    }
}

__global__ void scatter_kernel() {
    __shared__ int ka[CHUNK];
    int c = blockIdx.x;
    int t = threadIdx.x;
    int i = c * CHUNK + t;
    int k = g_asg[i];
    ka[t] = k;
    __syncthreads();
    int rank = 0;
    for (int j = 0; j < t; j++) rank += (ka[j] == k);
    g_order[g_hist[c * Kk + k] + rank] = i;
}

// grid (Kk, 4): block handles 128 dims of one cluster; thread = one dim
__global__ void update_kernel(const float* __restrict__ feats) {
    int k = blockIdx.x;
    int cnt = g_counts[k];
    if (cnt == 0) return;
    int start = g_offsets[k];
    int d = blockIdx.y * 128 + threadIdx.x;
    float inv = 1.0f / (float)cnt;
    float s = 0.f;
    for (int j = 0; j < cnt; j++)
        s += feats[(size_t)g_order[start + j] * Dd + d];
    g_cent[(size_t)k * Dd + d] = s * (float)cnt * inv * inv;
}

__global__ void dists_kernel(const float* __restrict__ feats) {
    int k = blockIdx.x;
    int cnt = g_counts[k];
    int start = g_offsets[k];
    int d = blockIdx.y * 128 + threadIdx.x;
    float c = g_cent[(size_t)k * Dd + d];
    float s = 0.f;
    for (int j = 0; j < cnt; j++) {
        float r = feats[(size_t)g_order[start + j] * Dd + d] - c;
        s = fmaf(r, r, s);
    }
    g_dists[(size_t)k * Dd + d] = s;
}

__global__ void reduce1_kernel() {
    double s = 0.0;
    int stride = gridDim.x * blockDim.x;
    for (int i = blockIdx.x * blockDim.x + threadIdx.x; i < Kk * Dd; i += stride)
        s += (double)expf(-g_dists[i] / CONCENTRATION);
    __shared__ double sm[256];
    sm[threadIdx.x] = s;
    __syncthreads();
    for (int o = 128; o; o >>= 1) {
        if (threadIdx.x < o) sm[threadIdx.x] += sm[threadIdx.x + o];
        __syncthreads();
    }
    if (threadIdx.x == 0) g_part1[blockIdx.x] = sm[0];
}

__global__ void finalize1_kernel() {
    __shared__ double sm[256];
    sm[threadIdx.x] = g_part1[threadIdx.x];
    __syncthreads();
    for (int o = 128; o; o >>= 1) {
        if (threadIdx.x < o) sm[threadIdx.x] += sm[threadIdx.x + o];
        __syncthreads();
    }
    if (threadIdx.x == 0) g_S = sm[0];
}

__global__ void reduce2_kernel() {
    float Sf = (float)g_S;
    double e1 = 0.0, e2 = 0.0;
    int stride = gridDim.x * blockDim.x;
    for (int i = blockIdx.x * blockDim.x + threadIdx.x; i < Kk * Dd; i += stride) {
        float dv = g_dists[i];
        float p  = expf(-dv / CONCENTRATION);
        float q  = p / Sf;
        e1 += (double)(q * logf(q + EPSf));
        float p2 = expf(-dv / TEMPERATURE);
        e2 += (double)logf(p2 + EPSf);
    }
    __shared__ double sa[256], sb[256];
    sa[threadIdx.x] = e1;
    sb[threadIdx.x] = e2;
    __syncthreads();
    for (int o = 128; o; o >>= 1) {
        if (threadIdx.x < o) {
            sa[threadIdx.x] += sa[threadIdx.x + o];
            sb[threadIdx.x] += sb[threadIdx.x + o];
        }
        __syncthreads();
    }
    if (threadIdx.x == 0) {
        g_part2a[blockIdx.x] = sa[0];
        g_part2b[blockIdx.x] = sb[0];
    }
}

__global__ void finalize2_kernel(float* __restrict__ out) {
    __shared__ double sa[256], sb[256];
    sa[threadIdx.x] = g_part2a[threadIdx.x];
    sb[threadIdx.x] = g_part2b[threadIdx.x];
    __syncthreads();
    for (int o = 128; o; o >>= 1) {
        if (threadIdx.x < o) {
            sa[threadIdx.x] += sa[threadIdx.x + o];
            sb[threadIdx.x] += sb[threadIdx.x + o];
        }
        __syncthreads();
    }
    if (threadIdx.x == 0) {
        double kd = (double)(Kk * Dd);
        double entropy = (sa[0] / kd);
        double nll = -(sb[0] / kd);
        out[0] = (float)(entropy + nll);
    }
}

extern "C" void kernel_launch(void* const* d_in, const int* in_sizes, int n_in,
                              void* d_out, int out_size) {
    const float* feats = (const float*)d_in[0];
    float* out = (float*)d_out;
    (void)in_sizes; (void)n_in; (void)out_size;

    static bool attr_done = false;
    if (!attr_done) {
        cudaFuncSetAttribute(assign_mma_kernel,
                             cudaFuncAttributeMaxDynamicSharedMemorySize, SMEM_BYTES);
        attr_done = true;
    }

    dim3 agrid(Nn / TM, Kk / TN);
    dim3 ugrid(Kk, 4);

    copy_init_kernel<<<(Kk * Dd + 255) / 256, 256>>>(feats);
    split_feats_kernel<<<(Nn * Dd + 255) / 256, 256>>>(feats);

    for (int it = 0; it < NUM_ITERS; it++) {
        split_csq_kernel<<<(Kk * 32) / 256, 256>>>();
        assign_mma_kernel<<<agrid, 256, SMEM_BYTES>>>();
        histo_kernel<<<NCHUNK, CHUNK>>>();
        scan_kernel<<<1, Kk>>>();
        bases_kernel<<<8, 128>>>();
        scatter_kernel<<<NCHUNK, CHUNK>>>();
        update_kernel<<<ugrid, 128>>>(feats);
    }

    split_csq_kernel<<<(Kk * 32) / 256, 256>>>();
    assign_mma_kernel<<<agrid, 256, SMEM_BYTES>>>();
    histo_kernel<<<NCHUNK, CHUNK>>>();
    scan_kernel<<<1, Kk>>>();
    bases_kernel<<<8, 128>>>();
    scatter_kernel<<<NCHUNK, CHUNK>>>();
    dists_kernel<<<ugrid, 128>>>(feats);

    reduce1_kernel<<<256, 256>>>();
    finalize1_kernel<<<1, 256>>>();
    reduce2_kernel<<<256, 256>>>();
    finalize2_kernel<<<1, 256>>>(out);
}